// round 5
// baseline (speedup 1.0000x reference)
#include <cuda_runtime.h>
#include <cuda_bf16.h>

// MaxPool3d kernel=2 stride=2 over [B=2, C=32, D=128, H=128, W=128] fp32.
// Output [2, 32, 64, 64, 64]. Pure HBM stream: 512 MiB read + 64 MiB write.
//
// R4: single-wave persistent kernel.
//  - 1024 CTAs x 256 threads (<=7 CTAs/SM, all resident in ONE wave:
//    no wave transitions, no dispatch tail, no ragged last wave)
//  - each thread processes exactly 16 output quads, iteration-major order
//    (iter * 262144 + global_tid) so the chip-wide read stream stays
//    sequential within each iteration wave
//  - unroll x2 -> 16 independent LDG.128 in flight per thread
//  - __ldcs/__stcs evict-first streaming (zero reuse)

#define IN_W 128
#define IN_HW (128 * 128)
#define IN_DHW (128 * 128 * 128)
#define OUT_W 64
#define OUT_HW (64 * 64)
#define OUT_DHW (64 * 64 * 64)

#define NBLK 1024
#define NTHR 256
#define NITER 16   // 4,194,304 quads / (1024*256 threads)

struct Quad { float4 v; float* dst; };

__device__ __forceinline__ void pool_one(const float* __restrict__ in,
                                         float* __restrict__ out,
                                         int t, float4& o, float*& dst)
{
    int w4 = t & 15;
    int h  = (t >> 4) & 63;
    int d  = (t >> 10) & 63;
    int bc = t >> 16;

    const float4* base = (const float4*)(in
        + (size_t)bc * IN_DHW
        + (size_t)(d << 1) * IN_HW
        + (size_t)(h << 1) * IN_W
        + (w4 << 3));

    float4 a0 = __ldcs(base + 0);
    float4 a1 = __ldcs(base + 1);
    float4 b0 = __ldcs(base + 32);
    float4 b1 = __ldcs(base + 33);
    float4 c0 = __ldcs(base + 4096);
    float4 c1 = __ldcs(base + 4097);
    float4 e0 = __ldcs(base + 4128);
    float4 e1 = __ldcs(base + 4129);

    float4 m0, m1;
    m0.x = fmaxf(fmaxf(a0.x, b0.x), fmaxf(c0.x, e0.x));
    m0.y = fmaxf(fmaxf(a0.y, b0.y), fmaxf(c0.y, e0.y));
    m0.z = fmaxf(fmaxf(a0.z, b0.z), fmaxf(c0.z, e0.z));
    m0.w = fmaxf(fmaxf(a0.w, b0.w), fmaxf(c0.w, e0.w));
    m1.x = fmaxf(fmaxf(a1.x, b1.x), fmaxf(c1.x, e1.x));
    m1.y = fmaxf(fmaxf(a1.y, b1.y), fmaxf(c1.y, e1.y));
    m1.z = fmaxf(fmaxf(a1.z, b1.z), fmaxf(c1.z, e1.z));
    m1.w = fmaxf(fmaxf(a1.w, b1.w), fmaxf(c1.w, e1.w));

    o.x = fmaxf(m0.x, m0.y);
    o.y = fmaxf(m0.z, m0.w);
    o.z = fmaxf(m1.x, m1.y);
    o.w = fmaxf(m1.z, m1.w);

    dst = out + (size_t)bc * OUT_DHW + (size_t)d * OUT_HW + (size_t)h * OUT_W + (w4 << 2);
}

__global__ __launch_bounds__(NTHR, 8) void maxpool3d_k2s2_kernel(
    const float* __restrict__ in, float* __restrict__ out)
{
    int gtid = blockIdx.x * NTHR + threadIdx.x;      // 0 .. 262143
    const int stride = NBLK * NTHR;                  // 262144

    #pragma unroll
    for (int it = 0; it < NITER; it += 2) {
        int t0 = it * stride + gtid;
        int t1 = (it + 1) * stride + gtid;

        float4 o0, o1;
        float *d0, *d1;
        pool_one(in, out, t0, o0, d0);
        pool_one(in, out, t1, o1, d1);

        __stcs((float4*)d0, o0);
        __stcs((float4*)d1, o1);
    }
}

extern "C" void kernel_launch(void* const* d_in, const int* in_sizes, int n_in,
                              void* d_out, int out_size)
{
    const float* in = (const float*)d_in[0];
    float* out = (float*)d_out;
    (void)in_sizes; (void)n_in; (void)out_size;

    maxpool3d_k2s2_kernel<<<NBLK, NTHR>>>(in, out);
}

// round 6
// speedup vs baseline: 1.0733x; 1.0733x over previous
#include <cuda_runtime.h>
#include <cuda_bf16.h>

// MaxPool3d kernel=2 stride=2 over [B=2, C=32, D=128, H=128, W=128] fp32.
// Output [2, 32, 64, 64, 64]. Pure HBM stream: 512 MiB read + 64 MiB write.
//
// R5: flat grid (no persistence — R4 showed loop-carry kills stream MLP),
// 8 outputs per thread along W:
//  - per row: 4 consecutive LDG.128 (64 B contiguous per thread,
//    2 KiB contiguous per warp per row) x 4 rows = 16 independent loads
//  - 2 consecutive STG.128 (32 B/thread, 1 KiB/warp contiguous)
//  - __ldcs/__stcs evict-first streaming
//  - 2,097,152 threads = 8192 blocks x 256, exact fit, no bounds check

#define IN_W 128
#define IN_HW (128 * 128)
#define IN_DHW (128 * 128 * 128)
#define OUT_W 64
#define OUT_HW (64 * 64)
#define OUT_DHW (64 * 64 * 64)

__device__ __forceinline__ float4 max4(float4 a, float4 b, float4 c, float4 d) {
    float4 r;
    r.x = fmaxf(fmaxf(a.x, b.x), fmaxf(c.x, d.x));
    r.y = fmaxf(fmaxf(a.y, b.y), fmaxf(c.y, d.y));
    r.z = fmaxf(fmaxf(a.z, b.z), fmaxf(c.z, d.z));
    r.w = fmaxf(fmaxf(a.w, b.w), fmaxf(c.w, d.w));
    return r;
}

__global__ __launch_bounds__(256) void maxpool3d_k2s2_kernel(
    const float* __restrict__ in, float* __restrict__ out)
{
    int t = blockIdx.x * 256 + threadIdx.x;   // 0 .. 2,097,151 (exact fit)

    int w8 = t & 7;                  // oct index along out W (8 per row of 64)
    int h  = (t >> 3) & 63;          // out h
    int d  = (t >> 9) & 63;          // out d
    int bc = t >> 15;                // plane (b*C + c), 0..63

    // Base of the 16-float input segment in row (2d, 2h).
    const float4* base = (const float4*)(in
        + (size_t)bc * IN_DHW
        + (size_t)(d << 1) * IN_HW
        + (size_t)(h << 1) * IN_W
        + (w8 << 4));

    // Row offsets in float4 units: +32 = next h row, +4096 = next d slab.
    // Front-batch all 16 independent streaming LDG.128 (MLP=16).
    float4 a0 = __ldcs(base + 0),    a1 = __ldcs(base + 1),
           a2 = __ldcs(base + 2),    a3 = __ldcs(base + 3);
    float4 b0 = __ldcs(base + 32),   b1 = __ldcs(base + 33),
           b2 = __ldcs(base + 34),   b3 = __ldcs(base + 35);
    float4 c0 = __ldcs(base + 4096), c1 = __ldcs(base + 4097),
           c2 = __ldcs(base + 4098), c3 = __ldcs(base + 4099);
    float4 e0 = __ldcs(base + 4128), e1 = __ldcs(base + 4129),
           e2 = __ldcs(base + 4130), e3 = __ldcs(base + 4131);

    // Reduce across the 4 (d,h) rows.
    float4 m0 = max4(a0, b0, c0, e0);
    float4 m1 = max4(a1, b1, c1, e1);
    float4 m2 = max4(a2, b2, c2, e2);
    float4 m3 = max4(a3, b3, c3, e3);

    // Pairwise max along W -> 8 outputs in two float4.
    float4 o0, o1;
    o0.x = fmaxf(m0.x, m0.y);  o0.y = fmaxf(m0.z, m0.w);
    o0.z = fmaxf(m1.x, m1.y);  o0.w = fmaxf(m1.z, m1.w);
    o1.x = fmaxf(m2.x, m2.y);  o1.y = fmaxf(m2.z, m2.w);
    o1.z = fmaxf(m3.x, m3.y);  o1.w = fmaxf(m3.z, m3.w);

    float4* op = (float4*)(out
        + (size_t)bc * OUT_DHW
        + (size_t)d * OUT_HW
        + (size_t)h * OUT_W
        + (w8 << 3));
    __stcs(op + 0, o0);
    __stcs(op + 1, o1);
}

extern "C" void kernel_launch(void* const* d_in, const int* in_sizes, int n_in,
                              void* d_out, int out_size)
{
    const float* in = (const float*)d_in[0];
    float* out = (float*)d_out;

    // out_size = 16,777,216 outputs -> 8 per thread -> 2,097,152 threads
    int blocks = (out_size / 8) / 256;   // 8192
    maxpool3d_k2s2_kernel<<<blocks, 256>>>(in, out);
}

// round 7
// speedup vs baseline: 1.1960x; 1.1143x over previous
#include <cuda_runtime.h>
#include <cuda_bf16.h>

// MaxPool3d kernel=2 stride=2 over [B=2, C=32, D=128, H=128, W=128] fp32.
// Output [2, 32, 64, 64, 64]. Pure HBM stream: 512 MiB read + 64 MiB write.
//
// R6: FINER granularity (R5's coarser direction regressed twice).
// 2 outputs per thread along W:
//  - 4 independent LDG.128 per thread (one float4 per (d,h) row), MLP_p1=4
//  - 1 STG.64 per thread (256 B/warp contiguous, fully coalesced)
//  - ~24 regs -> near-full occupancy, shallow per-thread L1tex queue
//  - 8,388,608 threads = 32768 blocks x 256, exact fit
//  - __ldcs/__stcs evict-first streaming

#define IN_W 128
#define IN_HW (128 * 128)
#define IN_DHW (128 * 128 * 128)
#define OUT_W 64
#define OUT_HW (64 * 64)
#define OUT_DHW (64 * 64 * 64)

__global__ __launch_bounds__(256) void maxpool3d_k2s2_kernel(
    const float* __restrict__ in, float* __restrict__ out)
{
    int t = blockIdx.x * 256 + threadIdx.x;   // 0 .. 8,388,607 (exact fit)

    int w2 = t & 31;                 // pair index along out W (32 per row of 64)
    int h  = (t >> 5) & 63;          // out h
    int d  = (t >> 11) & 63;         // out d
    int bc = t >> 17;                // plane (b*C + c), 0..63

    // 4 input floats per row starting at iw = w2*4.
    const float4* base = (const float4*)(in
        + (size_t)bc * IN_DHW
        + (size_t)(d << 1) * IN_HW
        + (size_t)(h << 1) * IN_W
        + (w2 << 2));

    // Row offsets in float4 units: +32 = next h row, +4096 = next d slab.
    // 4 independent streaming LDG.128.
    float4 a = __ldcs(base + 0);
    float4 b = __ldcs(base + 32);
    float4 c = __ldcs(base + 4096);
    float4 e = __ldcs(base + 4128);

    // Max across rows, then pairwise along W -> 2 outputs.
    float mx = fmaxf(fmaxf(a.x, b.x), fmaxf(c.x, e.x));
    float my = fmaxf(fmaxf(a.y, b.y), fmaxf(c.y, e.y));
    float mz = fmaxf(fmaxf(a.z, b.z), fmaxf(c.z, e.z));
    float mw = fmaxf(fmaxf(a.w, b.w), fmaxf(c.w, e.w));

    float2 o;
    o.x = fmaxf(mx, my);
    o.y = fmaxf(mz, mw);

    float2* op = (float2*)(out
        + (size_t)bc * OUT_DHW
        + (size_t)d * OUT_HW
        + (size_t)h * OUT_W
        + (w2 << 1));
    __stcs(op, o);
}

extern "C" void kernel_launch(void* const* d_in, const int* in_sizes, int n_in,
                              void* d_out, int out_size)
{
    const float* in = (const float*)d_in[0];
    float* out = (float*)d_out;

    // out_size = 16,777,216 outputs -> 2 per thread -> 8,388,608 threads
    int blocks = (out_size / 2) / 256;   // 32768
    maxpool3d_k2s2_kernel<<<blocks, 256>>>(in, out);
}